// round 1
// baseline (speedup 1.0000x reference)
#include <cuda_runtime.h>
#include <math.h>

#define BB 2
#define TT 2048
#define HIDDEN 1024
#define NH 16
#define DD 64
#define QKV_O 3072   // (16 + 2*16) * 64
#define MROWS (BB*TT) // 4096

// Scratch (allocation-free rule: __device__ globals)
__device__ float g_qkv[(size_t)MROWS * QKV_O];   // [B*T, 3072]
__device__ float g_ctx[(size_t)MROWS * HIDDEN];  // [B*T, 1024]

// ---------------------------------------------------------------------------
// SGEMM: C[M,N] = A[M,K] * B[N,K]^T   (all row-major, K % 16 == 0, M,N % 128 == 0)
// 128x128 tile, BK=16, 256 threads, 8x8 per thread.
// ---------------------------------------------------------------------------
__global__ __launch_bounds__(256) void sgemm_nt(const float* __restrict__ A,
                                                const float* __restrict__ Bm,
                                                float* __restrict__ C,
                                                int M, int N, int K)
{
    const int BM = 128, BN = 128, BK = 16;
    __shared__ float As[16][132];
    __shared__ float Bs[16][132];
    const int tid = threadIdx.x;
    const int tx = tid & 15;        // col group
    const int ty = tid >> 4;        // row group
    const int bm = blockIdx.y * BM;
    const int bn = blockIdx.x * BN;

    float acc[8][8];
#pragma unroll
    for (int i = 0; i < 8; i++)
#pragma unroll
        for (int j = 0; j < 8; j++) acc[i][j] = 0.f;

    for (int k0 = 0; k0 < K; k0 += BK) {
#pragma unroll
        for (int i = 0; i < 2; i++) {
            int v = tid + i * 256;            // 0..511
            int row = v >> 2;
            int kv  = (v & 3) << 2;
            float4 a4 = *(const float4*)&A[(size_t)(bm + row) * K + k0 + kv];
            As[kv + 0][row] = a4.x; As[kv + 1][row] = a4.y;
            As[kv + 2][row] = a4.z; As[kv + 3][row] = a4.w;
            float4 b4 = *(const float4*)&Bm[(size_t)(bn + row) * K + k0 + kv];
            Bs[kv + 0][row] = b4.x; Bs[kv + 1][row] = b4.y;
            Bs[kv + 2][row] = b4.z; Bs[kv + 3][row] = b4.w;
        }
        __syncthreads();
#pragma unroll
        for (int kk = 0; kk < BK; kk++) {
            float a[8], b[8];
#pragma unroll
            for (int i = 0; i < 4; i++) {
                a[i]     = As[kk][ty * 4 + i];
                a[i + 4] = As[kk][64 + ty * 4 + i];
                b[i]     = Bs[kk][tx * 4 + i];
                b[i + 4] = Bs[kk][64 + tx * 4 + i];
            }
#pragma unroll
            for (int i = 0; i < 8; i++)
#pragma unroll
                for (int j = 0; j < 8; j++)
                    acc[i][j] += a[i] * b[j];
        }
        __syncthreads();
    }

#pragma unroll
    for (int i = 0; i < 8; i++) {
        int row = bm + ((i < 4) ? (ty * 4 + i) : (64 + ty * 4 + (i - 4)));
#pragma unroll
        for (int j = 0; j < 8; j++) {
            int col = bn + ((j < 4) ? (tx * 4 + j) : (64 + tx * 4 + (j - 4)));
            C[(size_t)row * N + col] = acc[i][j];
        }
    }
}

// ---------------------------------------------------------------------------
// RoPE in-place on Q and K heads of qkv [B*T, 48, 64].
// One thread per (bt, head<32, half<32) pair.
// ---------------------------------------------------------------------------
__global__ __launch_bounds__(256) void rope_kernel(float* __restrict__ qkv,
                                                   const float* __restrict__ cos_t,
                                                   const float* __restrict__ sin_t)
{
    int idx = blockIdx.x * blockDim.x + threadIdx.x; // B*T*32*32
    int half = idx & 31;
    int rest = idx >> 5;
    int head = rest & 31;     // 0..31 : Q heads 0-15, K heads 16-31
    int bt   = rest >> 5;
    int t    = bt & (TT - 1);
    float c = cos_t[t * 64 + half];
    float s = sin_t[t * 64 + half];
    size_t base = ((size_t)bt * 48 + head) * 64;
    float x1 = qkv[base + half];
    float x2 = qkv[base + 32 + half];
    qkv[base + half]      = x1 * c - x2 * s;  // d < 32: x*c + (-x2)*s
    qkv[base + 32 + half] = x2 * c + x1 * s;  // d >=32: x*c + (x1)*s
}

// ---------------------------------------------------------------------------
// fp32 flash attention, causal. One block per (q-tile of 64, head, batch).
// 256 threads; thread (rg=tid/16, cg=tid%16) owns 4 rows x 4 cols.
// Dynamic smem: Qs,Ks,Vs,Ps each 64x65 floats.
// ---------------------------------------------------------------------------
#define LD 65
__global__ __launch_bounds__(256) void flash_attn(const float* __restrict__ qkv,
                                                  float* __restrict__ ctx)
{
    extern __shared__ float sm[];
    float* Qs = sm;
    float* Ks = Qs + 64 * LD;
    float* Vs = Ks + 64 * LD;
    float* Ps = Vs + 64 * LD;

    const int qt = blockIdx.x;
    const int h  = blockIdx.y;
    const int b  = blockIdx.z;
    const int tid = threadIdx.x;
    const int rg = tid >> 4;   // 0..15
    const int cg = tid & 15;   // 0..15

    // Load Q tile (scaled by 1/sqrt(D))
    const float scale = 0.125f;
#pragma unroll
    for (int i = 0; i < 16; i++) {
        int e = i * 256 + tid;
        int r = e >> 6, d = e & 63;
        int t = qt * 64 + r;
        Qs[r * LD + d] = qkv[(((size_t)(b * TT + t)) * 48 + h) * 64 + d] * scale;
    }

    float m[4]   = {-1e30f, -1e30f, -1e30f, -1e30f};
    float l[4]   = {0.f, 0.f, 0.f, 0.f};
    float o[4][4];
#pragma unroll
    for (int i = 0; i < 4; i++)
#pragma unroll
        for (int j = 0; j < 4; j++) o[i][j] = 0.f;

    __syncthreads();

    for (int kt = 0; kt <= qt; kt++) {
        // Load K, V tiles
#pragma unroll
        for (int i = 0; i < 16; i++) {
            int e = i * 256 + tid;
            int r = e >> 6, d = e & 63;
            int t = kt * 64 + r;
            size_t baseK = (((size_t)(b * TT + t)) * 48 + NH + h) * 64 + d;
            Ks[r * LD + d] = qkv[baseK];
            Vs[r * LD + d] = qkv[baseK + NH * 64];
        }
        __syncthreads();

        // S = Q K^T (4x4 per thread)
        float s[4][4];
#pragma unroll
        for (int i = 0; i < 4; i++)
#pragma unroll
            for (int j = 0; j < 4; j++) s[i][j] = 0.f;

        for (int d = 0; d < 64; d++) {
            float a0 = Qs[(rg * 4 + 0) * LD + d];
            float a1 = Qs[(rg * 4 + 1) * LD + d];
            float a2 = Qs[(rg * 4 + 2) * LD + d];
            float a3 = Qs[(rg * 4 + 3) * LD + d];
            float b0 = Ks[(cg * 4 + 0) * LD + d];
            float b1 = Ks[(cg * 4 + 1) * LD + d];
            float b2 = Ks[(cg * 4 + 2) * LD + d];
            float b3 = Ks[(cg * 4 + 3) * LD + d];
            s[0][0] += a0 * b0; s[0][1] += a0 * b1; s[0][2] += a0 * b2; s[0][3] += a0 * b3;
            s[1][0] += a1 * b0; s[1][1] += a1 * b1; s[1][2] += a1 * b2; s[1][3] += a1 * b3;
            s[2][0] += a2 * b0; s[2][1] += a2 * b1; s[2][2] += a2 * b2; s[2][3] += a2 * b3;
            s[3][0] += a3 * b0; s[3][1] += a3 * b1; s[3][2] += a3 * b2; s[3][3] += a3 * b3;
        }

        // Causal mask on the diagonal tile
        if (kt == qt) {
#pragma unroll
            for (int i = 0; i < 4; i++)
#pragma unroll
                for (int j = 0; j < 4; j++)
                    if (cg * 4 + j > rg * 4 + i) s[i][j] = -1e30f;
        }

        // Row max (across 4 local cols, then 16-lane group via shfl)
        float mx[4];
#pragma unroll
        for (int i = 0; i < 4; i++) {
            float v = fmaxf(fmaxf(s[i][0], s[i][1]), fmaxf(s[i][2], s[i][3]));
#pragma unroll
            for (int off = 1; off < 16; off <<= 1)
                v = fmaxf(v, __shfl_xor_sync(0xffffffffu, v, off));
            mx[i] = v;
        }

        // Online softmax update
        float alpha[4], rs[4];
#pragma unroll
        for (int i = 0; i < 4; i++) {
            float mn = fmaxf(m[i], mx[i]);
            alpha[i] = __expf(m[i] - mn);
            m[i] = mn;
            float acc = 0.f;
#pragma unroll
            for (int j = 0; j < 4; j++) {
                float p = __expf(s[i][j] - mn);
                s[i][j] = p;
                acc += p;
            }
#pragma unroll
            for (int off = 1; off < 16; off <<= 1)
                acc += __shfl_xor_sync(0xffffffffu, acc, off);
            rs[i] = acc;
        }
#pragma unroll
        for (int i = 0; i < 4; i++) {
            l[i] = l[i] * alpha[i] + rs[i];
#pragma unroll
            for (int j = 0; j < 4; j++) o[i][j] *= alpha[i];
            // Store P to smem (rows of this rg are written only by this warp's 16 lanes)
#pragma unroll
            for (int j = 0; j < 4; j++)
                Ps[(rg * 4 + i) * LD + cg * 4 + j] = s[i][j];
        }
        __syncwarp();

        // O += P @ V
        for (int c = 0; c < 64; c++) {
            float p0 = Ps[(rg * 4 + 0) * LD + c];
            float p1 = Ps[(rg * 4 + 1) * LD + c];
            float p2 = Ps[(rg * 4 + 2) * LD + c];
            float p3 = Ps[(rg * 4 + 3) * LD + c];
            float v0 = Vs[c * LD + cg * 4 + 0];
            float v1 = Vs[c * LD + cg * 4 + 1];
            float v2 = Vs[c * LD + cg * 4 + 2];
            float v3 = Vs[c * LD + cg * 4 + 3];
            o[0][0] += p0 * v0; o[0][1] += p0 * v1; o[0][2] += p0 * v2; o[0][3] += p0 * v3;
            o[1][0] += p1 * v0; o[1][1] += p1 * v1; o[1][2] += p1 * v2; o[1][3] += p1 * v3;
            o[2][0] += p2 * v0; o[2][1] += p2 * v1; o[2][2] += p2 * v2; o[2][3] += p2 * v3;
            o[3][0] += p3 * v0; o[3][1] += p3 * v1; o[3][2] += p3 * v2; o[3][3] += p3 * v3;
        }
        __syncthreads();   // before next iter overwrites Ks/Vs
    }

    // Epilogue: normalize + write ctx [B*T, H*D]
#pragma unroll
    for (int i = 0; i < 4; i++) {
        float inv = 1.f / l[i];
        int t = qt * 64 + rg * 4 + i;
        size_t base = ((size_t)(b * TT + t)) * HIDDEN + h * 64;
#pragma unroll
        for (int j = 0; j < 4; j++)
            ctx[base + cg * 4 + j] = o[i][j] * inv;
    }
}

// ---------------------------------------------------------------------------
extern "C" void kernel_launch(void* const* d_in, const int* in_sizes, int n_in,
                              void* d_out, int out_size)
{
    const float* hs    = (const float*)d_in[0];  // [B,T,1024]
    const float* cos_t = (const float*)d_in[1];  // [T,64]
    const float* sin_t = (const float*)d_in[2];  // [T,64]
    const float* wqkv  = (const float*)d_in[3];  // [3072,1024]
    const float* wo    = (const float*)d_in[4];  // [1024,1024]
    float* out = (float*)d_out;

    float* qkv = nullptr;
    float* ctx = nullptr;
    cudaGetSymbolAddress((void**)&qkv, g_qkv);
    cudaGetSymbolAddress((void**)&ctx, g_ctx);

    // 1) QKV = hs @ wqkv^T   [4096, 3072]
    sgemm_nt<<<dim3(QKV_O / 128, MROWS / 128), 256>>>(hs, wqkv, qkv, MROWS, QKV_O, HIDDEN);

    // 2) RoPE on Q and K heads
    rope_kernel<<<(BB * TT * 32 * 32) / 256, 256>>>(qkv, cos_t, sin_t);

    // 3) Flash attention -> ctx [4096, 1024]
    const int smem = 4 * 64 * LD * (int)sizeof(float);
    cudaFuncSetAttribute(flash_attn, cudaFuncAttributeMaxDynamicSharedMemorySize, smem);
    flash_attn<<<dim3(TT / 64, NH, BB), 256, smem>>>(qkv, ctx);

    // 4) out = ctx @ wo^T  [4096, 1024]
    sgemm_nt<<<dim3(HIDDEN / 128, MROWS / 128), 256>>>(ctx, wo, out, MROWS, HIDDEN, HIDDEN);
}